// round 6
// baseline (speedup 1.0000x reference)
#include <cuda_runtime.h>
#include <math.h>

#define NE   4096
#define EMB  64
#define NB   4
#define FCO  100
#define GRID 148
#define NTHR 512
#define NWARP 16
#define NITEM 1024          // NB * 64 row-tiles * 4 j-quarters
#define TBL_FLOATS (5 * NE)                       // q,q2,h0,h1,h2 = 80KB
#define RING_INTS (NWARP * 4 * 512)               // 16 warps x 4 slots x 2KB = 128KB
#define SMEM_BYTES (TBL_FLOATS * 4 + RING_INTS * 4)   // 208KB

// Scratch (allocation-free rule: __device__ globals)
__device__ float g_h0[NE], g_h1[NE], g_h2[NE];
__device__ float g_src[NE], g_dst[NE];
__device__ float g_x[NB * NE * 3];
__device__ float g_pS[4][NB * NE];
__device__ float g_pT0[4][NB * NE], g_pT1[4][NB * NE], g_pT2[4][NB * NE];
__device__ unsigned g_mbits = 0u;   // static init; atomicMax idempotent across replays

__device__ __forceinline__ unsigned enc_f(float f) {
    unsigned b = __float_as_uint(f);
    return (b & 0x80000000u) ? ~b : (b | 0x80000000u);
}
__device__ __forceinline__ float dec_f(unsigned u) {
    unsigned b = (u & 0x80000000u) ? (u & 0x7fffffffu) : ~u;
    return __uint_as_float(b);
}
__device__ __forceinline__ unsigned smem_u32(const void* p) {
    return (unsigned)__cvta_generic_to_shared(p);
}
__device__ __forceinline__ void cp16(unsigned dst, const void* src) {
    asm volatile("cp.async.cg.shared.global [%0], [%1], 16;" :: "r"(dst), "l"(src) : "memory");
}
__device__ __forceinline__ void cp_commit() {
    asm volatile("cp.async.commit_group;" ::: "memory");
}
__device__ __forceinline__ void cp_wait3() {
    asm volatile("cp.async.wait_group 3;" ::: "memory");
}
__device__ __forceinline__ void cp_wait0() {
    asm volatile("cp.async.wait_group 0;" ::: "memory");
}

// ---------------------------------------------------------------------------
// Kernel 1: h = emb @ W, src/dst projections, global max(dst) via atomicMax
__global__ void k_prep(const float* __restrict__ emb,
                       const float* __restrict__ W,
                       const float* __restrict__ av)
{
    int row = blockIdx.x * blockDim.x + threadIdx.x;
    if (row >= NE) return;
    const float* e = emb + row * EMB;
    float h0 = 0.f, h1 = 0.f, h2 = 0.f;
#pragma unroll
    for (int k = 0; k < EMB; k++) {
        float ev = __ldg(e + k);
        h0 = fmaf(ev, __ldg(W + k * 3 + 0), h0);
        h1 = fmaf(ev, __ldg(W + k * 3 + 1), h1);
        h2 = fmaf(ev, __ldg(W + k * 3 + 2), h2);
    }
    g_h0[row] = h0; g_h1[row] = h1; g_h2[row] = h2;
    g_src[row] = h0 * __ldg(av + 0) + h1 * __ldg(av + 1) + h2 * __ldg(av + 2);
    float d    = h0 * __ldg(av + 3) + h1 * __ldg(av + 4) + h2 * __ldg(av + 5);
    g_dst[row] = d;
    atomicMax(&g_mbits, enc_f(d));
}

// ---------------------------------------------------------------------------
// Kernel 2: persistent. Per-WARP private cp.async ring (no CTA barriers in loop).
// Item = (b, 64-row tile, j-quarter of 1024). 8 steps/item, 128 j each.
// Table LDS + m-precompute issued BEFORE the cp.async wait to hide latency.
// ---------------------------------------------------------------------------
__global__ void __launch_bounds__(NTHR, 1) k_main(const int* __restrict__ adj)
{
    extern __shared__ float sm[];
    float* sq  = sm;
    float* sq2 = sm + NE;
    float* sh0 = sm + 2 * NE;
    float* sh1 = sm + 3 * NE;
    float* sh2 = sm + 4 * NE;
    int*   ring = (int*)(sm + TBL_FLOATS);

    int tid = threadIdx.x, bid = blockIdx.x;
    int warp = tid >> 5, lane = tid & 31;

    // Preamble: per-CTA table build (q, q2, h copies)
    float Md = dec_f(g_mbits);
    for (int i = tid; i < NE; i += NTHR) {
        float d = g_dst[i];
        sq[i]  = expf(d - Md);
        sq2[i] = expf(0.2f * (d - Md));
        sh0[i] = g_h0[i]; sh1[i] = g_h1[i]; sh2[i] = g_h2[i];
    }
    __syncthreads();   // only barrier

    int nItems = 0;
    for (int it = bid; it < NITEM; it += GRID) nItems++;
    int total = nItems * 8;

    int* wring = ring + warp * 2048;                 // 4 slots x 512 ints
    unsigned ring_base = smem_u32(wring);

    auto issue = [&](int step) {
        int kIt = step >> 3;
        int it  = bid + kIt * GRID;
        int chunk = step & 7, slot = step & 3;
        int b = it >> 8, tile = (it >> 2) & 63, jq = it & 3;
        const int* src = adj
            + ((size_t)((b << 12) + (tile << 6) + (warp << 2))) * NE
            + (jq << 10) + (chunk << 7) + (lane << 2);
        unsigned dst = ring_base + (unsigned)slot * 2048u + (unsigned)(lane << 4);
#pragma unroll
        for (int r = 0; r < 4; r++)
            cp16(dst + (unsigned)r * 512u, src + (size_t)r * NE);
        cp_commit();
    };

    for (int p = 0; p < 3 && p < total; p++) issue(p);

    float S[4]  = {0, 0, 0, 0}, T0[4] = {0, 0, 0, 0};
    float T1[4] = {0, 0, 0, 0}, T2[4] = {0, 0, 0, 0};
    float Ca[4], Cb[4], W0[4];

    for (int step = 0; step < total; step++) {
        int kIt = step >> 3;
        int it  = bid + kIt * GRID;
        int chunk = step & 7, slot = step & 3;
        int b = it >> 8, tile = (it >> 2) & 63, jq = it & 3;
        int row0 = (tile << 6) + (warp << 2);

        if (chunk == 0) {
#pragma unroll
            for (int r = 0; r < 4; r++) {
                float z  = __ldg(&g_src[row0 + r]) + Md;
                float lr = z > 0.f ? z : 0.2f * z;
                float C  = fmaxf(lr, 9e-15f);
                Ca[r] = expf(z - C);
                Cb[r] = expf(0.2f * z - C);
                W0[r] = expf(9e-15f - C);
            }
        }

        // -------- independent work BEFORE the async-wait --------
        int jg = (jq << 10) + (chunk << 7) + (lane << 2);
        float4 Q  = *(const float4*)(sq  + jg);
        float4 Q2 = *(const float4*)(sq2 + jg);
        float4 H0 = *(const float4*)(sh0 + jg);
        float4 H1 = *(const float4*)(sh1 + jg);
        float4 H2 = *(const float4*)(sh2 + jg);
        float m[4][4];
#pragma unroll
        for (int r = 0; r < 4; r++) {
            m[r][0] = fmaxf(Ca[r] * Q.x, Cb[r] * Q2.x);
            m[r][1] = fmaxf(Ca[r] * Q.y, Cb[r] * Q2.y);
            m[r][2] = fmaxf(Ca[r] * Q.z, Cb[r] * Q2.z);
            m[r][3] = fmaxf(Ca[r] * Q.w, Cb[r] * Q2.w);
        }

        if (step + 3 < total) { issue(step + 3); cp_wait3(); }
        else                  { cp_wait0(); }
        __syncwarp();

        const int* st = wring + slot * 512;
#pragma unroll
        for (int r = 0; r < 4; r++) {
            int4 aa = *(const int4*)(st + (r << 7) + (lane << 2));
            float w0 = (aa.x > 0) ? m[r][0] : W0[r];
            float w1 = (aa.y > 0) ? m[r][1] : W0[r];
            float w2 = (aa.z > 0) ? m[r][2] : W0[r];
            float w3 = (aa.w > 0) ? m[r][3] : W0[r];
            S[r]  += (w0 + w1) + (w2 + w3);
            T0[r] = fmaf(w0, H0.x, fmaf(w1, H0.y, fmaf(w2, H0.z, fmaf(w3, H0.w, T0[r]))));
            T1[r] = fmaf(w0, H1.x, fmaf(w1, H1.y, fmaf(w2, H1.z, fmaf(w3, H1.w, T1[r]))));
            T2[r] = fmaf(w0, H2.x, fmaf(w1, H2.y, fmaf(w2, H2.z, fmaf(w3, H2.w, T2[r]))));
        }

        if (chunk == 7) {
#pragma unroll
            for (int o = 16; o > 0; o >>= 1) {
#pragma unroll
                for (int r = 0; r < 4; r++) {
                    S[r]  += __shfl_xor_sync(0xffffffffu, S[r],  o);
                    T0[r] += __shfl_xor_sync(0xffffffffu, T0[r], o);
                    T1[r] += __shfl_xor_sync(0xffffffffu, T1[r], o);
                    T2[r] += __shfl_xor_sync(0xffffffffu, T2[r], o);
                }
            }
            if (lane < 4) {
                int r = lane;
                int idx = (b << 12) + row0 + r;
                g_pS[jq][idx]  = S[r];
                g_pT0[jq][idx] = T0[r];
                g_pT1[jq][idx] = T1[r];
                g_pT2[jq][idx] = T2[r];
            }
#pragma unroll
            for (int r = 0; r < 4; r++) { S[r] = 0.f; T0[r] = 0.f; T1[r] = 0.f; T2[r] = 0.f; }
        }
    }
}

// ---------------------------------------------------------------------------
// Kernel 3: combine quarters, normalize, ELU
__global__ void k_elu()
{
    int t = blockIdx.x * blockDim.x + threadIdx.x;
    if (t >= NB * NE) return;
    float S  = (g_pS[0][t] + g_pS[1][t]) + (g_pS[2][t] + g_pS[3][t]);
    float inv = 1.f / S;
    float v0 = ((g_pT0[0][t] + g_pT0[1][t]) + (g_pT0[2][t] + g_pT0[3][t])) * inv;
    float v1 = ((g_pT1[0][t] + g_pT1[1][t]) + (g_pT1[2][t] + g_pT1[3][t])) * inv;
    float v2 = ((g_pT2[0][t] + g_pT2[1][t]) + (g_pT2[2][t] + g_pT2[3][t])) * inv;
    v0 = v0 > 0.f ? v0 : expm1f(v0);
    v1 = v1 > 0.f ? v1 : expm1f(v1);
    v2 = v2 > 0.f ? v2 : expm1f(v2);
    g_x[t * 3 + 0] = v0;
    g_x[t * 3 + 1] = v1;
    g_x[t * 3 + 2] = v2;
}

// ---------------------------------------------------------------------------
// Kernel 4: full FC in one kernel. grid=100 (one block per output k).
// Each block streams its whole 12288-float weight row (deep MLP), x is L2-hot.
__global__ void __launch_bounds__(256) k_fc(const float* __restrict__ w,
                                            const float* __restrict__ bias,
                                            float* __restrict__ out)
{
    int k = blockIdx.x;
    const float* wr = w + (size_t)k * (NE * 3);
    float a0 = 0.f, a1 = 0.f, a2 = 0.f, a3 = 0.f;
#pragma unroll
    for (int c = 0; c < 12; c++) {
        int n = c * 1024 + threadIdx.x * 4;
        float4 wv = __ldg((const float4*)(wr + n));
        float4 v0 = *(const float4*)(g_x + 0 * NE * 3 + n);
        float4 v1 = *(const float4*)(g_x + 1 * NE * 3 + n);
        float4 v2 = *(const float4*)(g_x + 2 * NE * 3 + n);
        float4 v3 = *(const float4*)(g_x + 3 * NE * 3 + n);
        a0 = fmaf(wv.x, v0.x, fmaf(wv.y, v0.y, fmaf(wv.z, v0.z, fmaf(wv.w, v0.w, a0))));
        a1 = fmaf(wv.x, v1.x, fmaf(wv.y, v1.y, fmaf(wv.z, v1.z, fmaf(wv.w, v1.w, a1))));
        a2 = fmaf(wv.x, v2.x, fmaf(wv.y, v2.y, fmaf(wv.z, v2.z, fmaf(wv.w, v2.w, a2))));
        a3 = fmaf(wv.x, v3.x, fmaf(wv.y, v3.y, fmaf(wv.z, v3.z, fmaf(wv.w, v3.w, a3))));
    }
#pragma unroll
    for (int o = 16; o > 0; o >>= 1) {
        a0 += __shfl_xor_sync(0xffffffffu, a0, o);
        a1 += __shfl_xor_sync(0xffffffffu, a1, o);
        a2 += __shfl_xor_sync(0xffffffffu, a2, o);
        a3 += __shfl_xor_sync(0xffffffffu, a3, o);
    }
    __shared__ float sred[4][8];
    int wrp = threadIdx.x >> 5, lane = threadIdx.x & 31;
    if (lane == 0) {
        sred[0][wrp] = a0; sred[1][wrp] = a1;
        sred[2][wrp] = a2; sred[3][wrp] = a3;
    }
    __syncthreads();
    if (threadIdx.x < 4) {
        float s = 0.f;
#pragma unroll
        for (int ww = 0; ww < 8; ww++) s += sred[threadIdx.x][ww];
        out[threadIdx.x * FCO + k] = s + __ldg(bias + k);
    }
}

// ---------------------------------------------------------------------------
extern "C" void kernel_launch(void* const* d_in, const int* in_sizes, int n_in,
                              void* d_out, int out_size)
{
    const int*   adj = (const int*)d_in[0];
    const float* emb = (const float*)d_in[1];
    const float* W   = (const float*)d_in[2];
    const float* av  = (const float*)d_in[3];
    const float* fcw = (const float*)d_in[4];
    const float* fcb = (const float*)d_in[5];
    float* out = (float*)d_out;

    cudaFuncSetAttribute(k_main, cudaFuncAttributeMaxDynamicSharedMemorySize,
                         SMEM_BYTES);

    k_prep<<<NE / 128, 128>>>(emb, W, av);
    k_main<<<GRID, NTHR, SMEM_BYTES>>>(adj);
    k_elu<<<NB * NE / 256, 256>>>();
    k_fc<<<FCO, 256>>>(fcw, fcb, out);
}

// round 7
// speedup vs baseline: 1.0295x; 1.0295x over previous
#include <cuda_runtime.h>
#include <math.h>

#define NE   4096
#define EMB  64
#define NB   4
#define FCO  100
#define GRID 148
#define NTHR 512
#define NWARP 16
#define NWSLOT (GRID * NWARP)     // 2368 warp slots
#define NITEM 16384               // NB * 1024 row-groups(4) * 4 j-quarters
#define NCHUNK 3
#define TBL_FLOATS (5 * NE)       // q,q2,h0,h1,h2 = 80KB
#define SMEM_BYTES (TBL_FLOATS * 4)

// Scratch (allocation-free rule: __device__ globals)
__device__ float g_h0[NE], g_h1[NE], g_h2[NE];
__device__ float g_src[NE], g_dst[NE];
__device__ float g_x[NB * NE * 3];
__device__ float g_part[NCHUNK * NB * FCO];
__device__ float g_pS[4][NB * NE];
__device__ float g_pT0[4][NB * NE], g_pT1[4][NB * NE], g_pT2[4][NB * NE];
__device__ unsigned g_mbits = 0u;   // static init; atomicMax idempotent across replays

__device__ __forceinline__ unsigned enc_f(float f) {
    unsigned b = __float_as_uint(f);
    return (b & 0x80000000u) ? ~b : (b | 0x80000000u);
}
__device__ __forceinline__ float dec_f(unsigned u) {
    unsigned b = (u & 0x80000000u) ? (u & 0x7fffffffu) : ~u;
    return __uint_as_float(b);
}

// ---------------------------------------------------------------------------
// Kernel 1: h = emb @ W, src/dst projections, global max(dst) via atomicMax
__global__ void k_prep(const float* __restrict__ emb,
                       const float* __restrict__ W,
                       const float* __restrict__ av)
{
    int row = blockIdx.x * blockDim.x + threadIdx.x;
    if (row >= NE) return;
    const float* e = emb + row * EMB;
    float h0 = 0.f, h1 = 0.f, h2 = 0.f;
#pragma unroll
    for (int k = 0; k < EMB; k++) {
        float ev = __ldg(e + k);
        h0 = fmaf(ev, __ldg(W + k * 3 + 0), h0);
        h1 = fmaf(ev, __ldg(W + k * 3 + 1), h1);
        h2 = fmaf(ev, __ldg(W + k * 3 + 2), h2);
    }
    g_h0[row] = h0; g_h1[row] = h1; g_h2[row] = h2;
    g_src[row] = h0 * __ldg(av + 0) + h1 * __ldg(av + 1) + h2 * __ldg(av + 2);
    float d    = h0 * __ldg(av + 3) + h1 * __ldg(av + 4) + h2 * __ldg(av + 5);
    g_dst[row] = d;
    atomicMax(&g_mbits, enc_f(d));
}

// ---------------------------------------------------------------------------
// Kernel 2: persistent, direct-LDG depth-2 pipeline, per-warp work items.
// Item = (b, 4-row group, j-quarter of 1024). 8 steps/item, 128 j each.
// 512 thr/CTA: 16 warps x 8 LDG.128 in flight = 64KB/SM. Tables in SMEM.
// ---------------------------------------------------------------------------
__global__ void __launch_bounds__(NTHR, 1) k_main(const int* __restrict__ adj)
{
    extern __shared__ float sm[];
    float* sq  = sm;
    float* sq2 = sm + NE;
    float* sh0 = sm + 2 * NE;
    float* sh1 = sm + 3 * NE;
    float* sh2 = sm + 4 * NE;

    int tid = threadIdx.x, bid = blockIdx.x;
    int warp = tid >> 5, lane = tid & 31;
    int wid = bid * NWARP + warp;

    float Md = dec_f(g_mbits);
    for (int i = tid; i < NE; i += NTHR) {
        float d = g_dst[i];
        sq[i]  = expf(d - Md);
        sq2[i] = expf(0.2f * (d - Md));
        sh0[i] = g_h0[i]; sh1[i] = g_h1[i]; sh2[i] = g_h2[i];
    }
    __syncthreads();   // only barrier

    int nItems = 0;
    for (int it = wid; it < NITEM; it += NWSLOT) nItems++;
    int total = nItems * 8;
    if (total == 0) return;

    // adj element offset for (step) at this lane, row r:
    //   it = wid + (step>>3)*NWSLOT; b=it>>12; grp=(it>>2)&1023; jq=it&3
    //   addr = ((b<<12) + (grp<<2) + r)*NE + (jq<<10) + ((step&7)<<7) + (lane<<2)
    auto ld4 = [&](int step, int4* dst) {
        int it = wid + (step >> 3) * NWSLOT;
        int b = it >> 12, grp = (it >> 2) & 1023, jq = it & 3;
        const int* src = adj
            + ((size_t)((b << 12) + (grp << 2))) * NE
            + (jq << 10) + ((step & 7) << 7) + (lane << 2);
#pragma unroll
        for (int r = 0; r < 4; r++)
            dst[r] = __ldcs((const int4*)(src + (size_t)r * NE));
    };

    int4 A[4], B[4], C[4];
    ld4(0, A);
    if (total > 1) ld4(1, B);

    float S[4]  = {0, 0, 0, 0}, T0[4] = {0, 0, 0, 0};
    float T1[4] = {0, 0, 0, 0}, T2[4] = {0, 0, 0, 0};
    float Ca[4], Cb[4], W0[4];

    for (int step = 0; step < total; step++) {
        int it = wid + (step >> 3) * NWSLOT;
        int chunk = step & 7;
        int b = it >> 12, grp = (it >> 2) & 1023, jq = it & 3;
        int row0 = grp << 2;

        if (chunk == 0) {
#pragma unroll
            for (int r = 0; r < 4; r++) {
                float z  = __ldg(&g_src[row0 + r]) + Md;
                float lr = z > 0.f ? z : 0.2f * z;
                float Cc = fmaxf(lr, 9e-15f);
                Ca[r] = expf(z - Cc);
                Cb[r] = expf(0.2f * z - Cc);
                W0[r] = expf(9e-15f - Cc);
            }
        }

        if (step + 2 < total) ld4(step + 2, C);

        int jg = (jq << 10) + (chunk << 7) + (lane << 2);
        float4 Q  = *(const float4*)(sq  + jg);
        float4 Q2 = *(const float4*)(sq2 + jg);
        float4 H0 = *(const float4*)(sh0 + jg);
        float4 H1 = *(const float4*)(sh1 + jg);
        float4 H2 = *(const float4*)(sh2 + jg);

#pragma unroll
        for (int r = 0; r < 4; r++) {
            float m0 = fmaxf(Ca[r] * Q.x, Cb[r] * Q2.x);
            float m1 = fmaxf(Ca[r] * Q.y, Cb[r] * Q2.y);
            float m2 = fmaxf(Ca[r] * Q.z, Cb[r] * Q2.z);
            float m3 = fmaxf(Ca[r] * Q.w, Cb[r] * Q2.w);
            float w0 = (A[r].x > 0) ? m0 : W0[r];
            float w1 = (A[r].y > 0) ? m1 : W0[r];
            float w2 = (A[r].z > 0) ? m2 : W0[r];
            float w3 = (A[r].w > 0) ? m3 : W0[r];
            S[r]  += (w0 + w1) + (w2 + w3);
            T0[r] = fmaf(w0, H0.x, fmaf(w1, H0.y, fmaf(w2, H0.z, fmaf(w3, H0.w, T0[r]))));
            T1[r] = fmaf(w0, H1.x, fmaf(w1, H1.y, fmaf(w2, H1.z, fmaf(w3, H1.w, T1[r]))));
            T2[r] = fmaf(w0, H2.x, fmaf(w1, H2.y, fmaf(w2, H2.z, fmaf(w3, H2.w, T2[r]))));
        }
#pragma unroll
        for (int r = 0; r < 4; r++) { A[r] = B[r]; B[r] = C[r]; }

        if (chunk == 7) {
#pragma unroll
            for (int o = 16; o > 0; o >>= 1) {
#pragma unroll
                for (int r = 0; r < 4; r++) {
                    S[r]  += __shfl_xor_sync(0xffffffffu, S[r],  o);
                    T0[r] += __shfl_xor_sync(0xffffffffu, T0[r], o);
                    T1[r] += __shfl_xor_sync(0xffffffffu, T1[r], o);
                    T2[r] += __shfl_xor_sync(0xffffffffu, T2[r], o);
                }
            }
            if (lane < 4) {
                int r = lane;
                int idx = (b << 12) + row0 + r;
                g_pS[jq][idx]  = S[r];
                g_pT0[jq][idx] = T0[r];
                g_pT1[jq][idx] = T1[r];
                g_pT2[jq][idx] = T2[r];
            }
#pragma unroll
            for (int r = 0; r < 4; r++) { S[r] = 0.f; T0[r] = 0.f; T1[r] = 0.f; T2[r] = 0.f; }
        }
    }
}

// ---------------------------------------------------------------------------
// Kernel 3: combine quarters, normalize, ELU
__global__ void k_elu()
{
    int t = blockIdx.x * blockDim.x + threadIdx.x;
    if (t >= NB * NE) return;
    float S  = (g_pS[0][t] + g_pS[1][t]) + (g_pS[2][t] + g_pS[3][t]);
    float inv = 1.f / S;
    float v0 = ((g_pT0[0][t] + g_pT0[1][t]) + (g_pT0[2][t] + g_pT0[3][t])) * inv;
    float v1 = ((g_pT1[0][t] + g_pT1[1][t]) + (g_pT1[2][t] + g_pT1[3][t])) * inv;
    float v2 = ((g_pT2[0][t] + g_pT2[1][t]) + (g_pT2[2][t] + g_pT2[3][t])) * inv;
    v0 = v0 > 0.f ? v0 : expm1f(v0);
    v1 = v1 > 0.f ? v1 : expm1f(v1);
    v2 = v2 > 0.f ? v2 : expm1f(v2);
    g_x[t * 3 + 0] = v0;
    g_x[t * 3 + 1] = v1;
    g_x[t * 3 + 2] = v2;
}

// ---------------------------------------------------------------------------
// Kernel 4a: partial FC. grid (100, 3); 4 independent w-float4 per thread.
__global__ void __launch_bounds__(256) k_fc1(const float* __restrict__ w)
{
    int k = blockIdx.x, c = blockIdx.y;
    const float* wr = w + (size_t)k * (NE * 3) + c * 4096;
    float a0 = 0.f, a1 = 0.f, a2 = 0.f, a3 = 0.f;
#pragma unroll
    for (int i = 0; i < 4; i++) {
        int n = i * 1024 + threadIdx.x * 4;
        float4 wv = __ldg((const float4*)(wr + n));
        int nx = c * 4096 + n;
        float4 v0 = *(const float4*)(g_x + 0 * NE * 3 + nx);
        float4 v1 = *(const float4*)(g_x + 1 * NE * 3 + nx);
        float4 v2 = *(const float4*)(g_x + 2 * NE * 3 + nx);
        float4 v3 = *(const float4*)(g_x + 3 * NE * 3 + nx);
        a0 = fmaf(wv.x, v0.x, fmaf(wv.y, v0.y, fmaf(wv.z, v0.z, fmaf(wv.w, v0.w, a0))));
        a1 = fmaf(wv.x, v1.x, fmaf(wv.y, v1.y, fmaf(wv.z, v1.z, fmaf(wv.w, v1.w, a1))));
        a2 = fmaf(wv.x, v2.x, fmaf(wv.y, v2.y, fmaf(wv.z, v2.z, fmaf(wv.w, v2.w, a2))));
        a3 = fmaf(wv.x, v3.x, fmaf(wv.y, v3.y, fmaf(wv.z, v3.z, fmaf(wv.w, v3.w, a3))));
    }
#pragma unroll
    for (int o = 16; o > 0; o >>= 1) {
        a0 += __shfl_xor_sync(0xffffffffu, a0, o);
        a1 += __shfl_xor_sync(0xffffffffu, a1, o);
        a2 += __shfl_xor_sync(0xffffffffu, a2, o);
        a3 += __shfl_xor_sync(0xffffffffu, a3, o);
    }
    __shared__ float sred[4][8];
    int wrp = threadIdx.x >> 5, lane = threadIdx.x & 31;
    if (lane == 0) {
        sred[0][wrp] = a0; sred[1][wrp] = a1;
        sred[2][wrp] = a2; sred[3][wrp] = a3;
    }
    __syncthreads();
    if (threadIdx.x < 4) {
        float s = 0.f;
#pragma unroll
        for (int ww = 0; ww < 8; ww++) s += sred[threadIdx.x][ww];
        g_part[(c * 4 + threadIdx.x) * FCO + k] = s;
    }
}

__global__ void k_fc2(const float* __restrict__ bias, float* __restrict__ out)
{
    int tid = threadIdx.x;
    if (tid >= NB * FCO) return;
    int b = tid / FCO, k = tid % FCO;
    float s = __ldg(bias + k);
#pragma unroll
    for (int c = 0; c < NCHUNK; c++) s += g_part[(c * 4 + b) * FCO + k];
    out[b * FCO + k] = s;
}

// ---------------------------------------------------------------------------
extern "C" void kernel_launch(void* const* d_in, const int* in_sizes, int n_in,
                              void* d_out, int out_size)
{
    const int*   adj = (const int*)d_in[0];
    const float* emb = (const float*)d_in[1];
    const float* W   = (const float*)d_in[2];
    const float* av  = (const float*)d_in[3];
    const float* fcw = (const float*)d_in[4];
    const float* fcb = (const float*)d_in[5];
    float* out = (float*)d_out;

    cudaFuncSetAttribute(k_main, cudaFuncAttributeMaxDynamicSharedMemorySize,
                         SMEM_BYTES);

    k_prep<<<NE / 128, 128>>>(emb, W, av);
    k_main<<<GRID, NTHR, SMEM_BYTES>>>(adj);
    k_elu<<<NB * NE / 256, 256>>>();
    k_fc1<<<dim3(FCO, NCHUNK), 256>>>(fcw);
    k_fc2<<<1, 512>>>(fcb, out);
}

// round 8
// speedup vs baseline: 1.0937x; 1.0623x over previous
#include <cuda_runtime.h>
#include <math.h>

#define NE   4096
#define EMB  64
#define NB   4
#define FCO  100
#define GRID 148
#define NTHR 512
#define NWARP 16
#define NWSLOT (GRID * NWARP)     // 2368 warp slots
#define NITEM 16384               // NB * 1024 row-groups(4) * 4 j-quarters
#define TBL_FLOATS (5 * NE)       // q,q2,h0,h1,h2 = 80KB
#define SMEM_BYTES (TBL_FLOATS * 4)
#define KG 4                       // k outputs per FC block
#define NCH 12                     // FC chunks

// Scratch (allocation-free rule: __device__ globals)
__device__ float g_h0[NE], g_h1[NE], g_h2[NE];
__device__ float g_src[NE], g_dst[NE];
__device__ float g_x[NB * NE * 3];
__device__ float g_part[NCH * FCO * NB];
__device__ float g_pS[4][NB * NE];
__device__ float g_pT0[4][NB * NE], g_pT1[4][NB * NE], g_pT2[4][NB * NE];
__device__ unsigned g_mbits = 0u;   // static init; atomicMax idempotent across replays

__device__ __forceinline__ unsigned enc_f(float f) {
    unsigned b = __float_as_uint(f);
    return (b & 0x80000000u) ? ~b : (b | 0x80000000u);
}
__device__ __forceinline__ float dec_f(unsigned u) {
    unsigned b = (u & 0x80000000u) ? (u & 0x7fffffffu) : ~u;
    return __uint_as_float(b);
}

// Packed f32x2 helpers (sm_103a)
typedef unsigned long long ull;
__device__ __forceinline__ ull pack2(float lo, float hi) {
    ull r; asm("mov.b64 %0, {%1, %2};" : "=l"(r) : "f"(lo), "f"(hi)); return r;
}
__device__ __forceinline__ void unpack2(float& lo, float& hi, ull v) {
    asm("mov.b64 {%0, %1}, %2;" : "=f"(lo), "=f"(hi) : "l"(v));
}
__device__ __forceinline__ ull mul2(ull a, ull b) {
    ull d; asm("mul.rn.f32x2 %0, %1, %2;" : "=l"(d) : "l"(a), "l"(b)); return d;
}
#define FMA_X2(d, a, b, c) \
    asm("fma.rn.f32x2 %0, %1, %2, %3;" : "=l"(d) : "l"(a), "l"(b), "l"(c))
#define ADD_X2(d, a, b) \
    asm("add.rn.f32x2 %0, %1, %2;" : "=l"(d) : "l"(a), "l"(b))

// ---------------------------------------------------------------------------
// Kernel 1: h = emb @ W (4 threads/row), src/dst, global max(dst)
__global__ void __launch_bounds__(256) k_prep(const float* __restrict__ emb,
                                              const float* __restrict__ W,
                                              const float* __restrict__ av)
{
    int t = blockIdx.x * 256 + threadIdx.x;
    int row = t >> 2, sub = t & 3;
    const float4* e4 = (const float4*)(emb + row * EMB);
    float h0 = 0.f, h1 = 0.f, h2 = 0.f;
#pragma unroll
    for (int i = 0; i < 4; i++) {
        int fi = sub + i * 4;
        float4 ev = __ldg(e4 + fi);
        int k = fi * 4;
        h0 = fmaf(ev.x, __ldg(W + (k+0)*3+0), h0); h1 = fmaf(ev.x, __ldg(W + (k+0)*3+1), h1); h2 = fmaf(ev.x, __ldg(W + (k+0)*3+2), h2);
        h0 = fmaf(ev.y, __ldg(W + (k+1)*3+0), h0); h1 = fmaf(ev.y, __ldg(W + (k+1)*3+1), h1); h2 = fmaf(ev.y, __ldg(W + (k+1)*3+2), h2);
        h0 = fmaf(ev.z, __ldg(W + (k+2)*3+0), h0); h1 = fmaf(ev.z, __ldg(W + (k+2)*3+1), h1); h2 = fmaf(ev.z, __ldg(W + (k+2)*3+2), h2);
        h0 = fmaf(ev.w, __ldg(W + (k+3)*3+0), h0); h1 = fmaf(ev.w, __ldg(W + (k+3)*3+1), h1); h2 = fmaf(ev.w, __ldg(W + (k+3)*3+2), h2);
    }
#pragma unroll
    for (int o = 1; o <= 2; o <<= 1) {
        h0 += __shfl_xor_sync(0xffffffffu, h0, o);
        h1 += __shfl_xor_sync(0xffffffffu, h1, o);
        h2 += __shfl_xor_sync(0xffffffffu, h2, o);
    }
    if (sub == 0) {
        g_h0[row] = h0; g_h1[row] = h1; g_h2[row] = h2;
        g_src[row] = h0 * __ldg(av + 0) + h1 * __ldg(av + 1) + h2 * __ldg(av + 2);
        float d    = h0 * __ldg(av + 3) + h1 * __ldg(av + 4) + h2 * __ldg(av + 5);
        g_dst[row] = d;
        atomicMax(&g_mbits, enc_f(d));
    }
}

// ---------------------------------------------------------------------------
// Kernel 2: persistent, direct-LDG depth-2, packed f32x2 accumulation.
// Item = (b, 4-row group, j-quarter). 8 steps of 128 j.
// Half-warp split: lanes 0-15 own rows {0,1}, lanes 16-31 own rows {2,3}.
// Lane covers j = lsub*4 + f*64, f in {0,1}.
// ---------------------------------------------------------------------------
__global__ void __launch_bounds__(NTHR, 1) k_main(const int* __restrict__ adj)
{
    extern __shared__ float sm[];
    float* sq  = sm;
    float* sq2 = sm + NE;
    float* sh0 = sm + 2 * NE;
    float* sh1 = sm + 3 * NE;
    float* sh2 = sm + 4 * NE;

    int tid = threadIdx.x, bid = blockIdx.x;
    int warp = tid >> 5, lane = tid & 31;
    int half = lane >> 4, lsub = lane & 15;
    int wid = bid * NWARP + warp;

    float Md = dec_f(g_mbits);
    for (int i = tid; i < NE; i += NTHR) {
        float d = g_dst[i];
        sq[i]  = expf(d - Md);
        sq2[i] = expf(0.2f * (d - Md));
        sh0[i] = g_h0[i]; sh1[i] = g_h1[i]; sh2[i] = g_h2[i];
    }
    __syncthreads();   // only barrier

    int nItems = 0;
    for (int it = wid; it < NITEM; it += NWSLOT) nItems++;
    int total = nItems * 8;
    if (total == 0) return;

    // load one step: 4 LDG.128 into dst[rr][f]
    auto ld = [&](int step, int4 (*dst)[2]) {
        int it = wid + (step >> 3) * NWSLOT;
        int b = it >> 12, grp = (it >> 2) & 1023, jq = it & 3;
        const int* base = adj
            + ((size_t)((b << 12) + (grp << 2) + (half << 1))) * NE
            + (jq << 10) + ((step & 7) << 7) + (lsub << 2);
        dst[0][0] = __ldcs((const int4*)(base));
        dst[0][1] = __ldcs((const int4*)(base + 64));
        dst[1][0] = __ldcs((const int4*)(base + NE));
        dst[1][1] = __ldcs((const int4*)(base + NE + 64));
    };

    int4 A[2][2], B[2][2], C[2][2];
    ld(0, A);
    if (total > 1) ld(1, B);

    ull Sp[2] = {0ull, 0ull}, T0p[2] = {0ull, 0ull};
    ull T1p[2] = {0ull, 0ull}, T2p[2] = {0ull, 0ull};
    ull Ca2[2], Cb2[2];
    float W0s[2];

    for (int step = 0; step < total; step++) {
        int it = wid + (step >> 3) * NWSLOT;
        int chunk = step & 7;
        int b = it >> 12, grp = (it >> 2) & 1023, jq = it & 3;
        int row0 = (grp << 2) + (half << 1);

        if (chunk == 0) {
#pragma unroll
            for (int rr = 0; rr < 2; rr++) {
                float z  = __ldg(&g_src[row0 + rr]) + Md;
                float lr = z > 0.f ? z : 0.2f * z;
                float Cc = fmaxf(lr, 9e-15f);
                float ca = expf(z - Cc), cb = expf(0.2f * z - Cc);
                Ca2[rr] = pack2(ca, ca);
                Cb2[rr] = pack2(cb, cb);
                W0s[rr] = expf(9e-15f - Cc);
            }
        }

        if (step + 2 < total) ld(step + 2, C);

#pragma unroll
        for (int f = 0; f < 2; f++) {
            int jg = (jq << 10) + (chunk << 7) + (f << 6) + (lsub << 2);
            double2 Qd  = *(const double2*)(sq  + jg);
            double2 Q2d = *(const double2*)(sq2 + jg);
            double2 H0d = *(const double2*)(sh0 + jg);
            double2 H1d = *(const double2*)(sh1 + jg);
            double2 H2d = *(const double2*)(sh2 + jg);
            ull qlo  = __double_as_longlong(Qd.x),  qhi  = __double_as_longlong(Qd.y);
            ull q2lo = __double_as_longlong(Q2d.x), q2hi = __double_as_longlong(Q2d.y);
            ull h0lo = __double_as_longlong(H0d.x), h0hi = __double_as_longlong(H0d.y);
            ull h1lo = __double_as_longlong(H1d.x), h1hi = __double_as_longlong(H1d.y);
            ull h2lo = __double_as_longlong(H2d.x), h2hi = __double_as_longlong(H2d.y);
#pragma unroll
            for (int rr = 0; rr < 2; rr++) {
                int4 aa = A[rr][f];
                // pair 0 (j, j+1)
                {
                    ull t1 = mul2(Ca2[rr], qlo), t2 = mul2(Cb2[rr], q2lo);
                    float m0, m1, n0, n1;
                    unpack2(m0, m1, t1); unpack2(n0, n1, t2);
                    float w0 = (aa.x > 0) ? fmaxf(m0, n0) : W0s[rr];
                    float w1 = (aa.y > 0) ? fmaxf(m1, n1) : W0s[rr];
                    ull wp = pack2(w0, w1);
                    ADD_X2(Sp[rr], Sp[rr], wp);
                    FMA_X2(T0p[rr], wp, h0lo, T0p[rr]);
                    FMA_X2(T1p[rr], wp, h1lo, T1p[rr]);
                    FMA_X2(T2p[rr], wp, h2lo, T2p[rr]);
                }
                // pair 1 (j+2, j+3)
                {
                    ull t1 = mul2(Ca2[rr], qhi), t2 = mul2(Cb2[rr], q2hi);
                    float m0, m1, n0, n1;
                    unpack2(m0, m1, t1); unpack2(n0, n1, t2);
                    float w0 = (aa.z > 0) ? fmaxf(m0, n0) : W0s[rr];
                    float w1 = (aa.w > 0) ? fmaxf(m1, n1) : W0s[rr];
                    ull wp = pack2(w0, w1);
                    ADD_X2(Sp[rr], Sp[rr], wp);
                    FMA_X2(T0p[rr], wp, h0hi, T0p[rr]);
                    FMA_X2(T1p[rr], wp, h1hi, T1p[rr]);
                    FMA_X2(T2p[rr], wp, h2hi, T2p[rr]);
                }
            }
        }
#pragma unroll
        for (int rr = 0; rr < 2; rr++)
#pragma unroll
            for (int f = 0; f < 2; f++) { A[rr][f] = B[rr][f]; B[rr][f] = C[rr][f]; }

        if (chunk == 7) {
            // fold packed pairs, then half-warp (16-lane) reduce
            float S[2], T0[2], T1[2], T2[2];
#pragma unroll
            for (int rr = 0; rr < 2; rr++) {
                float lo, hi;
                unpack2(lo, hi, Sp[rr]);  S[rr]  = lo + hi;
                unpack2(lo, hi, T0p[rr]); T0[rr] = lo + hi;
                unpack2(lo, hi, T1p[rr]); T1[rr] = lo + hi;
                unpack2(lo, hi, T2p[rr]); T2[rr] = lo + hi;
                Sp[rr] = 0ull; T0p[rr] = 0ull; T1p[rr] = 0ull; T2p[rr] = 0ull;
            }
#pragma unroll
            for (int o = 8; o > 0; o >>= 1) {
#pragma unroll
                for (int rr = 0; rr < 2; rr++) {
                    S[rr]  += __shfl_xor_sync(0xffffffffu, S[rr],  o);
                    T0[rr] += __shfl_xor_sync(0xffffffffu, T0[rr], o);
                    T1[rr] += __shfl_xor_sync(0xffffffffu, T1[rr], o);
                    T2[rr] += __shfl_xor_sync(0xffffffffu, T2[rr], o);
                }
            }
            if (lsub == 0) {
#pragma unroll
                for (int rr = 0; rr < 2; rr++) {
                    int idx = (b << 12) + row0 + rr;
                    g_pS[jq][idx]  = S[rr];
                    g_pT0[jq][idx] = T0[rr];
                    g_pT1[jq][idx] = T1[rr];
                    g_pT2[jq][idx] = T2[rr];
                }
            }
        }
    }
}

// ---------------------------------------------------------------------------
// Kernel 3: combine quarters, normalize, ELU
__global__ void k_elu()
{
    int t = blockIdx.x * blockDim.x + threadIdx.x;
    if (t >= NB * NE) return;
    float S  = (g_pS[0][t] + g_pS[1][t]) + (g_pS[2][t] + g_pS[3][t]);
    float inv = 1.f / S;
    float v0 = ((g_pT0[0][t] + g_pT0[1][t]) + (g_pT0[2][t] + g_pT0[3][t])) * inv;
    float v1 = ((g_pT1[0][t] + g_pT1[1][t]) + (g_pT1[2][t] + g_pT1[3][t])) * inv;
    float v2 = ((g_pT2[0][t] + g_pT2[1][t]) + (g_pT2[2][t] + g_pT2[3][t])) * inv;
    v0 = v0 > 0.f ? v0 : expm1f(v0);
    v1 = v1 > 0.f ? v1 : expm1f(v1);
    v2 = v2 > 0.f ? v2 : expm1f(v2);
    g_x[t * 3 + 0] = v0;
    g_x[t * 3 + 1] = v1;
    g_x[t * 3 + 2] = v2;
}

// ---------------------------------------------------------------------------
// Kernel 4a: FC partial, KG=4 outputs per block share SMEM-staged x chunk.
// grid (25, 12): (kgroup, chunk). chunk = 1024 floats.
__global__ void __launch_bounds__(256) k_fc1(const float* __restrict__ w)
{
    __shared__ float sx[NB][1024];
    __shared__ float sr[8][16];
    int kg = blockIdx.x, c = blockIdx.y;
    int tid = threadIdx.x;
    int n = c * 1024 + tid * 4;

    float4 wv[KG];
#pragma unroll
    for (int kk = 0; kk < KG; kk++)
        wv[kk] = __ldg((const float4*)(w + (size_t)(kg * KG + kk) * (NE * 3) + n));
#pragma unroll
    for (int b = 0; b < NB; b++)
        *(float4*)&sx[b][tid * 4] = *(const float4*)(g_x + b * NE * 3 + n);
    __syncthreads();

    float acc[KG][NB];
#pragma unroll
    for (int kk = 0; kk < KG; kk++)
#pragma unroll
        for (int b = 0; b < NB; b++) {
            float4 xv = *(const float4*)&sx[b][tid * 4];
            acc[kk][b] = fmaf(wv[kk].x, xv.x, fmaf(wv[kk].y, xv.y,
                         fmaf(wv[kk].z, xv.z, wv[kk].w * xv.w)));
        }
#pragma unroll
    for (int o = 16; o > 0; o >>= 1)
#pragma unroll
        for (int kk = 0; kk < KG; kk++)
#pragma unroll
            for (int b = 0; b < NB; b++)
                acc[kk][b] += __shfl_xor_sync(0xffffffffu, acc[kk][b], o);

    int wrp = tid >> 5, lane = tid & 31;
    if (lane == 0) {
#pragma unroll
        for (int kk = 0; kk < KG; kk++)
#pragma unroll
            for (int b = 0; b < NB; b++)
                sr[wrp][kk * NB + b] = acc[kk][b];
    }
    __syncthreads();
    if (tid < KG * NB) {
        float s = 0.f;
#pragma unroll
        for (int ww = 0; ww < 8; ww++) s += sr[ww][tid];
        int kk = tid >> 2, b = tid & 3;
        g_part[c * (FCO * NB) + (kg * KG + kk) * NB + b] = s;
    }
}

__global__ void k_fc2(const float* __restrict__ bias, float* __restrict__ out)
{
    int tid = threadIdx.x;
    if (tid >= FCO * NB) return;
    int k = tid >> 2, b = tid & 3;
    float s = __ldg(bias + k);
#pragma unroll
    for (int c = 0; c < NCH; c++) s += g_part[c * (FCO * NB) + k * NB + b];
    out[b * FCO + k] = s;
}

// ---------------------------------------------------------------------------
extern "C" void kernel_launch(void* const* d_in, const int* in_sizes, int n_in,
                              void* d_out, int out_size)
{
    const int*   adj = (const int*)d_in[0];
    const float* emb = (const float*)d_in[1];
    const float* W   = (const float*)d_in[2];
    const float* av  = (const float*)d_in[3];
    const float* fcw = (const float*)d_in[4];
    const float* fcb = (const float*)d_in[5];
    float* out = (float*)d_out;

    cudaFuncSetAttribute(k_main, cudaFuncAttributeMaxDynamicSharedMemorySize,
                         SMEM_BYTES);

    k_prep<<<NE * 4 / 256, 256>>>(emb, W, av);
    k_main<<<GRID, NTHR, SMEM_BYTES>>>(adj);
    k_elu<<<NB * NE / 256, 256>>>();
    k_fc1<<<dim3(FCO / KG, NCH), 256>>>(fcw);
    k_fc2<<<1, 512>>>(fcb, out);
}

// round 9
// speedup vs baseline: 1.0974x; 1.0034x over previous
#include <cuda_runtime.h>
#include <math.h>

#define NE   4096
#define EMB  64
#define NB   4
#define FCO  100
#define GRID 148
#define NTHR 512
#define NWARP 16
#define NWSLOT (GRID * NWARP)     // 2368 warp slots
#define NITEM 16384               // NB * 1024 row-groups(4) * 4 j-quarters
#define TBL_FLOATS (5 * NE)       // q,q2,h0,h1,h2 = 80KB
#define SMEM_BYTES (TBL_FLOATS * 4)
#define KG 4                       // k outputs per FC block
#define NCH 6                      // FC chunks (2048 floats each)

// Scratch (allocation-free rule: __device__ globals)
__device__ float g_h0[NE], g_h1[NE], g_h2[NE];
__device__ float g_src[NE], g_dst[NE];
__device__ float g_x[NB * NE * 3];
__device__ float g_part[NCH * FCO * NB];
__device__ float g_pS[4][NB * NE];
__device__ float g_pT0[4][NB * NE], g_pT1[4][NB * NE], g_pT2[4][NB * NE];
__device__ unsigned g_mbits = 0u;   // static init; atomicMax idempotent across replays

__device__ __forceinline__ unsigned enc_f(float f) {
    unsigned b = __float_as_uint(f);
    return (b & 0x80000000u) ? ~b : (b | 0x80000000u);
}
__device__ __forceinline__ float dec_f(unsigned u) {
    unsigned b = (u & 0x80000000u) ? (u & 0x7fffffffu) : ~u;
    return __uint_as_float(b);
}

// Packed f32x2 helpers (sm_103a)
typedef unsigned long long ull;
__device__ __forceinline__ ull pack2(float lo, float hi) {
    ull r; asm("mov.b64 %0, {%1, %2};" : "=l"(r) : "f"(lo), "f"(hi)); return r;
}
__device__ __forceinline__ void unpack2(float& lo, float& hi, ull v) {
    asm("mov.b64 {%0, %1}, %2;" : "=f"(lo), "=f"(hi) : "l"(v));
}
__device__ __forceinline__ ull mul2(ull a, ull b) {
    ull d; asm("mul.rn.f32x2 %0, %1, %2;" : "=l"(d) : "l"(a), "l"(b)); return d;
}
#define FMA_X2(d, a, b, c) \
    asm("fma.rn.f32x2 %0, %1, %2, %3;" : "=l"(d) : "l"(a), "l"(b), "l"(c))
#define ADD_X2(d, a, b) \
    asm("add.rn.f32x2 %0, %1, %2;" : "=l"(d) : "l"(a), "l"(b))

// ---------------------------------------------------------------------------
// Kernel 1: h = emb @ W (4 threads/row), src/dst, global max(dst)
__global__ void __launch_bounds__(256) k_prep(const float* __restrict__ emb,
                                              const float* __restrict__ W,
                                              const float* __restrict__ av)
{
    int t = blockIdx.x * 256 + threadIdx.x;
    int row = t >> 2, sub = t & 3;
    const float4* e4 = (const float4*)(emb + row * EMB);
    float h0 = 0.f, h1 = 0.f, h2 = 0.f;
#pragma unroll
    for (int i = 0; i < 4; i++) {
        int fi = sub + i * 4;
        float4 ev = __ldg(e4 + fi);
        int k = fi * 4;
        h0 = fmaf(ev.x, __ldg(W + (k+0)*3+0), h0); h1 = fmaf(ev.x, __ldg(W + (k+0)*3+1), h1); h2 = fmaf(ev.x, __ldg(W + (k+0)*3+2), h2);
        h0 = fmaf(ev.y, __ldg(W + (k+1)*3+0), h0); h1 = fmaf(ev.y, __ldg(W + (k+1)*3+1), h1); h2 = fmaf(ev.y, __ldg(W + (k+1)*3+2), h2);
        h0 = fmaf(ev.z, __ldg(W + (k+2)*3+0), h0); h1 = fmaf(ev.z, __ldg(W + (k+2)*3+1), h1); h2 = fmaf(ev.z, __ldg(W + (k+2)*3+2), h2);
        h0 = fmaf(ev.w, __ldg(W + (k+3)*3+0), h0); h1 = fmaf(ev.w, __ldg(W + (k+3)*3+1), h1); h2 = fmaf(ev.w, __ldg(W + (k+3)*3+2), h2);
    }
#pragma unroll
    for (int o = 1; o <= 2; o <<= 1) {
        h0 += __shfl_xor_sync(0xffffffffu, h0, o);
        h1 += __shfl_xor_sync(0xffffffffu, h1, o);
        h2 += __shfl_xor_sync(0xffffffffu, h2, o);
    }
    if (sub == 0) {
        g_h0[row] = h0; g_h1[row] = h1; g_h2[row] = h2;
        g_src[row] = h0 * __ldg(av + 0) + h1 * __ldg(av + 1) + h2 * __ldg(av + 2);
        float d    = h0 * __ldg(av + 3) + h1 * __ldg(av + 4) + h2 * __ldg(av + 5);
        g_dst[row] = d;
        atomicMax(&g_mbits, enc_f(d));
    }
}

// ---------------------------------------------------------------------------
// Kernel 2: persistent, direct-LDG DEPTH-3, packed f32x2 accumulation.
// Item = (b, 4-row group, j-quarter). 8 steps of 128 j.
// Half-warp split: lanes 0-15 own rows {0,1}, lanes 16-31 own rows {2,3}.
// ---------------------------------------------------------------------------
__global__ void __launch_bounds__(NTHR, 1) k_main(const int* __restrict__ adj)
{
    extern __shared__ float sm[];
    float* sq  = sm;
    float* sq2 = sm + NE;
    float* sh0 = sm + 2 * NE;
    float* sh1 = sm + 3 * NE;
    float* sh2 = sm + 4 * NE;

    int tid = threadIdx.x, bid = blockIdx.x;
    int warp = tid >> 5, lane = tid & 31;
    int half = lane >> 4, lsub = lane & 15;
    int wid = bid * NWARP + warp;

    float Md = dec_f(g_mbits);
    for (int i = tid; i < NE; i += NTHR) {
        float d = g_dst[i];
        sq[i]  = expf(d - Md);
        sq2[i] = expf(0.2f * (d - Md));
        sh0[i] = g_h0[i]; sh1[i] = g_h1[i]; sh2[i] = g_h2[i];
    }
    __syncthreads();   // only barrier

    int nItems = 0;
    for (int it = wid; it < NITEM; it += NWSLOT) nItems++;
    int total = nItems * 8;
    if (total == 0) return;

    auto ld = [&](int step, int4 (*dst)[2]) {
        int it = wid + (step >> 3) * NWSLOT;
        int b = it >> 12, grp = (it >> 2) & 1023, jq = it & 3;
        const int* base = adj
            + ((size_t)((b << 12) + (grp << 2) + (half << 1))) * NE
            + (jq << 10) + ((step & 7) << 7) + (lsub << 2);
        dst[0][0] = __ldcs((const int4*)(base));
        dst[0][1] = __ldcs((const int4*)(base + 64));
        dst[1][0] = __ldcs((const int4*)(base + NE));
        dst[1][1] = __ldcs((const int4*)(base + NE + 64));
    };

    int4 A[2][2], B[2][2], C[2][2], D[2][2];
    ld(0, A);
    if (total > 1) ld(1, B);
    if (total > 2) ld(2, C);

    ull Sp[2] = {0ull, 0ull}, T0p[2] = {0ull, 0ull};
    ull T1p[2] = {0ull, 0ull}, T2p[2] = {0ull, 0ull};
    ull Ca2[2], Cb2[2];
    float W0s[2];

    for (int step = 0; step < total; step++) {
        int it = wid + (step >> 3) * NWSLOT;
        int chunk = step & 7;
        int b = it >> 12, grp = (it >> 2) & 1023, jq = it & 3;
        int row0 = (grp << 2) + (half << 1);

        if (chunk == 0) {
#pragma unroll
            for (int rr = 0; rr < 2; rr++) {
                float z  = __ldg(&g_src[row0 + rr]) + Md;
                float lr = z > 0.f ? z : 0.2f * z;
                float Cc = fmaxf(lr, 9e-15f);
                float ca = expf(z - Cc), cb = expf(0.2f * z - Cc);
                Ca2[rr] = pack2(ca, ca);
                Cb2[rr] = pack2(cb, cb);
                W0s[rr] = expf(9e-15f - Cc);
            }
        }

        if (step + 3 < total) ld(step + 3, D);

#pragma unroll
        for (int f = 0; f < 2; f++) {
            int jg = (jq << 10) + (chunk << 7) + (f << 6) + (lsub << 2);
            double2 Qd  = *(const double2*)(sq  + jg);
            double2 Q2d = *(const double2*)(sq2 + jg);
            double2 H0d = *(const double2*)(sh0 + jg);
            double2 H1d = *(const double2*)(sh1 + jg);
            double2 H2d = *(const double2*)(sh2 + jg);
            ull qlo  = __double_as_longlong(Qd.x),  qhi  = __double_as_longlong(Qd.y);
            ull q2lo = __double_as_longlong(Q2d.x), q2hi = __double_as_longlong(Q2d.y);
            ull h0lo = __double_as_longlong(H0d.x), h0hi = __double_as_longlong(H0d.y);
            ull h1lo = __double_as_longlong(H1d.x), h1hi = __double_as_longlong(H1d.y);
            ull h2lo = __double_as_longlong(H2d.x), h2hi = __double_as_longlong(H2d.y);
#pragma unroll
            for (int rr = 0; rr < 2; rr++) {
                int4 aa = A[rr][f];
                {
                    ull t1 = mul2(Ca2[rr], qlo), t2 = mul2(Cb2[rr], q2lo);
                    float m0, m1, n0, n1;
                    unpack2(m0, m1, t1); unpack2(n0, n1, t2);
                    float w0 = (aa.x > 0) ? fmaxf(m0, n0) : W0s[rr];
                    float w1 = (aa.y > 0) ? fmaxf(m1, n1) : W0s[rr];
                    ull wp = pack2(w0, w1);
                    ADD_X2(Sp[rr], Sp[rr], wp);
                    FMA_X2(T0p[rr], wp, h0lo, T0p[rr]);
                    FMA_X2(T1p[rr], wp, h1lo, T1p[rr]);
                    FMA_X2(T2p[rr], wp, h2lo, T2p[rr]);
                }
                {
                    ull t1 = mul2(Ca2[rr], qhi), t2 = mul2(Cb2[rr], q2hi);
                    float m0, m1, n0, n1;
                    unpack2(m0, m1, t1); unpack2(n0, n1, t2);
                    float w0 = (aa.z > 0) ? fmaxf(m0, n0) : W0s[rr];
                    float w1 = (aa.w > 0) ? fmaxf(m1, n1) : W0s[rr];
                    ull wp = pack2(w0, w1);
                    ADD_X2(Sp[rr], Sp[rr], wp);
                    FMA_X2(T0p[rr], wp, h0hi, T0p[rr]);
                    FMA_X2(T1p[rr], wp, h1hi, T1p[rr]);
                    FMA_X2(T2p[rr], wp, h2hi, T2p[rr]);
                }
            }
        }
#pragma unroll
        for (int rr = 0; rr < 2; rr++)
#pragma unroll
            for (int f = 0; f < 2; f++) {
                A[rr][f] = B[rr][f]; B[rr][f] = C[rr][f]; C[rr][f] = D[rr][f];
            }

        if (chunk == 7) {
            float S[2], T0[2], T1[2], T2[2];
#pragma unroll
            for (int rr = 0; rr < 2; rr++) {
                float lo, hi;
                unpack2(lo, hi, Sp[rr]);  S[rr]  = lo + hi;
                unpack2(lo, hi, T0p[rr]); T0[rr] = lo + hi;
                unpack2(lo, hi, T1p[rr]); T1[rr] = lo + hi;
                unpack2(lo, hi, T2p[rr]); T2[rr] = lo + hi;
                Sp[rr] = 0ull; T0p[rr] = 0ull; T1p[rr] = 0ull; T2p[rr] = 0ull;
            }
#pragma unroll
            for (int o = 8; o > 0; o >>= 1) {
#pragma unroll
                for (int rr = 0; rr < 2; rr++) {
                    S[rr]  += __shfl_xor_sync(0xffffffffu, S[rr],  o);
                    T0[rr] += __shfl_xor_sync(0xffffffffu, T0[rr], o);
                    T1[rr] += __shfl_xor_sync(0xffffffffu, T1[rr], o);
                    T2[rr] += __shfl_xor_sync(0xffffffffu, T2[rr], o);
                }
            }
            if (lsub == 0) {
#pragma unroll
                for (int rr = 0; rr < 2; rr++) {
                    int idx = (b << 12) + row0 + rr;
                    g_pS[jq][idx]  = S[rr];
                    g_pT0[jq][idx] = T0[rr];
                    g_pT1[jq][idx] = T1[rr];
                    g_pT2[jq][idx] = T2[rr];
                }
            }
        }
    }
}

// ---------------------------------------------------------------------------
// Kernel 3: combine quarters, normalize, ELU
__global__ void k_elu()
{
    int t = blockIdx.x * blockDim.x + threadIdx.x;
    if (t >= NB * NE) return;
    float S  = (g_pS[0][t] + g_pS[1][t]) + (g_pS[2][t] + g_pS[3][t]);
    float inv = 1.f / S;
    float v0 = ((g_pT0[0][t] + g_pT0[1][t]) + (g_pT0[2][t] + g_pT0[3][t])) * inv;
    float v1 = ((g_pT1[0][t] + g_pT1[1][t]) + (g_pT1[2][t] + g_pT1[3][t])) * inv;
    float v2 = ((g_pT2[0][t] + g_pT2[1][t]) + (g_pT2[2][t] + g_pT2[3][t])) * inv;
    v0 = v0 > 0.f ? v0 : expm1f(v0);
    v1 = v1 > 0.f ? v1 : expm1f(v1);
    v2 = v2 > 0.f ? v2 : expm1f(v2);
    g_x[t * 3 + 0] = v0;
    g_x[t * 3 + 1] = v1;
    g_x[t * 3 + 2] = v2;
}

// ---------------------------------------------------------------------------
// Kernel 4a: FC partial. grid (25, 6): (kgroup of 4, chunk of 2048 floats).
// 16 front-batched independent LDG.128 per thread (8 w + 8 x), x L2-hot.
__global__ void __launch_bounds__(256) k_fc1(const float* __restrict__ w)
{
    __shared__ float sr[8][16];
    int kg = blockIdx.x, c = blockIdx.y;
    int tid = threadIdx.x;
    int n0 = c * 2048 + tid * 4;

    float4 wv[KG][2];
#pragma unroll
    for (int kk = 0; kk < KG; kk++) {
        const float* wr = w + (size_t)(kg * KG + kk) * (NE * 3);
        wv[kk][0] = __ldg((const float4*)(wr + n0));
        wv[kk][1] = __ldg((const float4*)(wr + n0 + 1024));
    }
    float4 xv[NB][2];
#pragma unroll
    for (int b = 0; b < NB; b++) {
        xv[b][0] = *(const float4*)(g_x + b * NE * 3 + n0);
        xv[b][1] = *(const float4*)(g_x + b * NE * 3 + n0 + 1024);
    }

    float acc[KG][NB];
#pragma unroll
    for (int kk = 0; kk < KG; kk++)
#pragma unroll
        for (int b = 0; b < NB; b++) {
            float a = fmaf(wv[kk][0].x, xv[b][0].x, fmaf(wv[kk][0].y, xv[b][0].y,
                      fmaf(wv[kk][0].z, xv[b][0].z, wv[kk][0].w * xv[b][0].w)));
            a = fmaf(wv[kk][1].x, xv[b][1].x, fmaf(wv[kk][1].y, xv[b][1].y,
                fmaf(wv[kk][1].z, xv[b][1].z, fmaf(wv[kk][1].w, xv[b][1].w, a))));
            acc[kk][b] = a;
        }
#pragma unroll
    for (int o = 16; o > 0; o >>= 1)
#pragma unroll
        for (int kk = 0; kk < KG; kk++)
#pragma unroll
            for (int b = 0; b < NB; b++)
                acc[kk][b] += __shfl_xor_sync(0xffffffffu, acc[kk][b], o);

    int wrp = tid >> 5, lane = tid & 31;
    if (lane == 0) {
#pragma unroll
        for (int kk = 0; kk < KG; kk++)
#pragma unroll
            for (int b = 0; b < NB; b++)
                sr[wrp][kk * NB + b] = acc[kk][b];
    }
    __syncthreads();
    if (tid < KG * NB) {
        float s = 0.f;
#pragma unroll
        for (int ww = 0; ww < 8; ww++) s += sr[ww][tid];
        int kk = tid >> 2, b = tid & 3;
        g_part[c * (FCO * NB) + (kg * KG + kk) * NB + b] = s;
    }
}

__global__ void k_fc2(const float* __restrict__ bias, float* __restrict__ out)
{
    int tid = threadIdx.x;
    if (tid >= FCO * NB) return;
    int k = tid >> 2, b = tid & 3;
    float s = __ldg(bias + k);
#pragma unroll
    for (int c = 0; c < NCH; c++) s += g_part[c * (FCO * NB) + k * NB + b];
    out[b * FCO + k] = s;
}

// ---------------------------------------------------------------------------
extern "C" void kernel_launch(void* const* d_in, const int* in_sizes, int n_in,
                              void* d_out, int out_size)
{
    const int*   adj = (const int*)d_in[0];
    const float* emb = (const float*)d_in[1];
    const float* W   = (const float*)d_in[2];
    const float* av  = (const float*)d_in[3];
    const float* fcw = (const float*)d_in[4];
    const float* fcb = (const float*)d_in[5];
    float* out = (float*)d_out;

    cudaFuncSetAttribute(k_main, cudaFuncAttributeMaxDynamicSharedMemorySize,
                         SMEM_BYTES);

    k_prep<<<NE * 4 / 256, 256>>>(emb, W, av);
    k_main<<<GRID, NTHR, SMEM_BYTES>>>(adj);
    k_elu<<<NB * NE / 256, 256>>>();
    k_fc1<<<dim3(FCO / KG, NCH), 256>>>(fcw);
    k_fc2<<<1, 512>>>(fcb, out);
}

// round 10
// speedup vs baseline: 1.1405x; 1.0393x over previous
#include <cuda_runtime.h>
#include <math.h>

#define NE   4096
#define EMB  64
#define NB   4
#define FCO  100
#define GRID 148
#define NTHR 512
#define NWARP 16
#define NWSLOT (GRID * NWARP)     // 2368 warp slots
#define NITEM 16384               // NB * 512 row-groups(8) * 8 j-eighths
#define TBL_FLOATS (5 * NE)       // q,q2,h0,h1,h2 = 80KB
#define RING_INTS (NWARP * 4 * 512)   // 16 warps x 4 slots x 2KB = 128KB
#define SMEM_BYTES (TBL_FLOATS * 4 + RING_INTS * 4)  // 208KB
#define KG 4
#define NCH 6

// Scratch (allocation-free rule: __device__ globals)
__device__ float g_h0[NE], g_h1[NE], g_h2[NE];
__device__ float g_src[NE], g_dst[NE];
__device__ float g_x[NB * NE * 3];
__device__ float g_part[NCH * FCO * NB];
__device__ float g_pS[8][NB * NE];
__device__ float g_pT0[8][NB * NE], g_pT1[8][NB * NE], g_pT2[8][NB * NE];
__device__ unsigned g_mbits = 0u;   // static init; atomicMax idempotent across replays

__device__ __forceinline__ unsigned enc_f(float f) {
    unsigned b = __float_as_uint(f);
    return (b & 0x80000000u) ? ~b : (b | 0x80000000u);
}
__device__ __forceinline__ float dec_f(unsigned u) {
    unsigned b = (u & 0x80000000u) ? (u & 0x7fffffffu) : ~u;
    return __uint_as_float(b);
}
__device__ __forceinline__ unsigned smem_u32(const void* p) {
    return (unsigned)__cvta_generic_to_shared(p);
}
__device__ __forceinline__ void cp16(unsigned dst, const void* src) {
    asm volatile("cp.async.cg.shared.global [%0], [%1], 16;" :: "r"(dst), "l"(src) : "memory");
}
__device__ __forceinline__ void cp_commit() {
    asm volatile("cp.async.commit_group;" ::: "memory");
}
__device__ __forceinline__ void cp_wait3() {
    asm volatile("cp.async.wait_group 3;" ::: "memory");
}
__device__ __forceinline__ void cp_wait0() {
    asm volatile("cp.async.wait_group 0;" ::: "memory");
}

// Packed f32x2 helpers (sm_103a)
typedef unsigned long long ull;
__device__ __forceinline__ ull pack2(float lo, float hi) {
    ull r; asm("mov.b64 %0, {%1, %2};" : "=l"(r) : "f"(lo), "f"(hi)); return r;
}
__device__ __forceinline__ void unpack2(float& lo, float& hi, ull v) {
    asm("mov.b64 {%0, %1}, %2;" : "=f"(lo), "=f"(hi) : "l"(v));
}
__device__ __forceinline__ ull mul2(ull a, ull b) {
    ull d; asm("mul.rn.f32x2 %0, %1, %2;" : "=l"(d) : "l"(a), "l"(b)); return d;
}
#define FMA_X2(d, a, b, c) \
    asm("fma.rn.f32x2 %0, %1, %2, %3;" : "=l"(d) : "l"(a), "l"(b), "l"(c))
#define ADD_X2(d, a, b) \
    asm("add.rn.f32x2 %0, %1, %2;" : "=l"(d) : "l"(a), "l"(b))

// ---------------------------------------------------------------------------
// Kernel 1: h = emb @ W (4 threads/row), src/dst, global max(dst)
__global__ void __launch_bounds__(256) k_prep(const float* __restrict__ emb,
                                              const float* __restrict__ W,
                                              const float* __restrict__ av)
{
    int t = blockIdx.x * 256 + threadIdx.x;
    int row = t >> 2, sub = t & 3;
    const float4* e4 = (const float4*)(emb + row * EMB);
    float h0 = 0.f, h1 = 0.f, h2 = 0.f;
#pragma unroll
    for (int i = 0; i < 4; i++) {
        int fi = sub + i * 4;
        float4 ev = __ldg(e4 + fi);
        int k = fi * 4;
        h0 = fmaf(ev.x, __ldg(W + (k+0)*3+0), h0); h1 = fmaf(ev.x, __ldg(W + (k+0)*3+1), h1); h2 = fmaf(ev.x, __ldg(W + (k+0)*3+2), h2);
        h0 = fmaf(ev.y, __ldg(W + (k+1)*3+0), h0); h1 = fmaf(ev.y, __ldg(W + (k+1)*3+1), h1); h2 = fmaf(ev.y, __ldg(W + (k+1)*3+2), h2);
        h0 = fmaf(ev.z, __ldg(W + (k+2)*3+0), h0); h1 = fmaf(ev.z, __ldg(W + (k+2)*3+1), h1); h2 = fmaf(ev.z, __ldg(W + (k+2)*3+2), h2);
        h0 = fmaf(ev.w, __ldg(W + (k+3)*3+0), h0); h1 = fmaf(ev.w, __ldg(W + (k+3)*3+1), h1); h2 = fmaf(ev.w, __ldg(W + (k+3)*3+2), h2);
    }
#pragma unroll
    for (int o = 1; o <= 2; o <<= 1) {
        h0 += __shfl_xor_sync(0xffffffffu, h0, o);
        h1 += __shfl_xor_sync(0xffffffffu, h1, o);
        h2 += __shfl_xor_sync(0xffffffffu, h2, o);
    }
    if (sub == 0) {
        g_h0[row] = h0; g_h1[row] = h1; g_h2[row] = h2;
        g_src[row] = h0 * __ldg(av + 0) + h1 * __ldg(av + 1) + h2 * __ldg(av + 2);
        float d    = h0 * __ldg(av + 3) + h1 * __ldg(av + 4) + h2 * __ldg(av + 5);
        g_dst[row] = d;
        atomicMax(&g_mbits, enc_f(d));
    }
}

// ---------------------------------------------------------------------------
// Kernel 2: persistent; per-warp cp.async ring (4 x 2KB), f32x2 math, 8-row items.
// Item = (b, 8-row group, j-eighth of 512). 8 steps of 64 j x 8 rows = 2KB.
// cp map: lane l stages row (l>>2), bytes (l&3)*16 + k*64, k=0..3.
// compute map: lanes 0-15 rows 0-3, lanes 16-31 rows 4-7; lsub covers 4 j.
// ---------------------------------------------------------------------------
__global__ void __launch_bounds__(NTHR, 1) k_main(const int* __restrict__ adj)
{
    extern __shared__ float sm[];
    float* sq  = sm;
    float* sq2 = sm + NE;
    float* sh0 = sm + 2 * NE;
    float* sh1 = sm + 3 * NE;
    float* sh2 = sm + 4 * NE;
    int*   ring = (int*)(sm + TBL_FLOATS);

    int tid = threadIdx.x, bid = blockIdx.x;
    int warp = tid >> 5, lane = tid & 31;
    int lsub = lane & 15, halfr0 = (lane >> 4) << 2;
    int wid = bid * NWARP + warp;

    float Md = dec_f(g_mbits);
    for (int i = tid; i < NE; i += NTHR) {
        float d = g_dst[i];
        sq[i]  = expf(d - Md);
        sq2[i] = expf(0.2f * (d - Md));
        sh0[i] = g_h0[i]; sh1[i] = g_h1[i]; sh2[i] = g_h2[i];
    }
    __syncthreads();   // only barrier

    int nItems = 0;
    for (int it = wid; it < NITEM; it += NWSLOT) nItems++;
    int total = nItems * 8;
    if (total == 0) return;

    int* wring = ring + warp * 2048;              // 4 slots x 512 ints
    int cp_row = lane >> 2, cp_col = (lane & 3) << 2;   // ints
    unsigned cp_dst0 = smem_u32(wring) + (unsigned)((cp_row << 6) + cp_col) * 4u;

    auto issue = [&](int step) {
        int it = wid + (step >> 3) * NWSLOT;
        int slot = step & 3;
        int b = it >> 12, grp = (it >> 3) & 511, je = it & 7;
        const int* src = adj
            + ((size_t)((b << 12) + (grp << 3) + cp_row)) * NE
            + (je << 9) + ((step & 7) << 6) + cp_col;
        unsigned dst = cp_dst0 + (unsigned)slot * 2048u;
#pragma unroll
        for (int k = 0; k < 4; k++)
            cp16(dst + k * 64u, src + k * 16);
        cp_commit();
    };

    for (int p = 0; p < 3 && p < total; p++) issue(p);

    ull Sp[4] = {0,0,0,0}, T0p[4] = {0,0,0,0}, T1p[4] = {0,0,0,0}, T2p[4] = {0,0,0,0};
    ull Ca2[4], Cb2[4];
    float W0s[4];

    for (int step = 0; step < total; step++) {
        int it = wid + (step >> 3) * NWSLOT;
        int chunk = step & 7, slot = step & 3;
        int b = it >> 12, grp = (it >> 3) & 511, je = it & 7;
        int row0 = (grp << 3) + halfr0;

        if (chunk == 0) {
#pragma unroll
            for (int rr = 0; rr < 4; rr++) {
                float z  = __ldg(&g_src[row0 + rr]) + Md;
                float lr = z > 0.f ? z : 0.2f * z;
                float Cc = fmaxf(lr, 9e-15f);
                float ca = expf(z - Cc), cb = expf(0.2f * z - Cc);
                Ca2[rr] = pack2(ca, ca);
                Cb2[rr] = pack2(cb, cb);
                W0s[rr] = expf(9e-15f - Cc);
            }
        }

        // independent table loads + m-precompute BEFORE the wait
        int jg = (je << 9) + (chunk << 6) + (lsub << 2);
        double2 Qd  = *(const double2*)(sq  + jg);
        double2 Q2d = *(const double2*)(sq2 + jg);
        double2 H0d = *(const double2*)(sh0 + jg);
        double2 H1d = *(const double2*)(sh1 + jg);
        double2 H2d = *(const double2*)(sh2 + jg);
        ull qlo  = __double_as_longlong(Qd.x),  qhi  = __double_as_longlong(Qd.y);
        ull q2lo = __double_as_longlong(Q2d.x), q2hi = __double_as_longlong(Q2d.y);
        ull h0lo = __double_as_longlong(H0d.x), h0hi = __double_as_longlong(H0d.y);
        ull h1lo = __double_as_longlong(H1d.x), h1hi = __double_as_longlong(H1d.y);
        ull h2lo = __double_as_longlong(H2d.x), h2hi = __double_as_longlong(H2d.y);

        if (step + 3 < total) { issue(step + 3); cp_wait3(); }
        else                  { cp_wait0(); }
        __syncwarp();

        const int* st = wring + slot * 512;
#pragma unroll
        for (int rr = 0; rr < 4; rr++) {
            int4 aa = *(const int4*)(st + ((halfr0 + rr) << 6) + (lsub << 2));
            {
                ull t1 = mul2(Ca2[rr], qlo), t2 = mul2(Cb2[rr], q2lo);
                float m0, m1, n0, n1;
                unpack2(m0, m1, t1); unpack2(n0, n1, t2);
                float w0 = (aa.x > 0) ? fmaxf(m0, n0) : W0s[rr];
                float w1 = (aa.y > 0) ? fmaxf(m1, n1) : W0s[rr];
                ull wp = pack2(w0, w1);
                ADD_X2(Sp[rr], Sp[rr], wp);
                FMA_X2(T0p[rr], wp, h0lo, T0p[rr]);
                FMA_X2(T1p[rr], wp, h1lo, T1p[rr]);
                FMA_X2(T2p[rr], wp, h2lo, T2p[rr]);
            }
            {
                ull t1 = mul2(Ca2[rr], qhi), t2 = mul2(Cb2[rr], q2hi);
                float m0, m1, n0, n1;
                unpack2(m0, m1, t1); unpack2(n0, n1, t2);
                float w0 = (aa.z > 0) ? fmaxf(m0, n0) : W0s[rr];
                float w1 = (aa.w > 0) ? fmaxf(m1, n1) : W0s[rr];
                ull wp = pack2(w0, w1);
                ADD_X2(Sp[rr], Sp[rr], wp);
                FMA_X2(T0p[rr], wp, h0hi, T0p[rr]);
                FMA_X2(T1p[rr], wp, h1hi, T1p[rr]);
                FMA_X2(T2p[rr], wp, h2hi, T2p[rr]);
            }
        }

        if (chunk == 7) {
            float S[4], T0[4], T1[4], T2[4];
#pragma unroll
            for (int rr = 0; rr < 4; rr++) {
                float lo, hi;
                unpack2(lo, hi, Sp[rr]);  S[rr]  = lo + hi;
                unpack2(lo, hi, T0p[rr]); T0[rr] = lo + hi;
                unpack2(lo, hi, T1p[rr]); T1[rr] = lo + hi;
                unpack2(lo, hi, T2p[rr]); T2[rr] = lo + hi;
                Sp[rr] = 0ull; T0p[rr] = 0ull; T1p[rr] = 0ull; T2p[rr] = 0ull;
            }
#pragma unroll
            for (int o = 8; o > 0; o >>= 1) {
#pragma unroll
                for (int rr = 0; rr < 4; rr++) {
                    S[rr]  += __shfl_xor_sync(0xffffffffu, S[rr],  o);
                    T0[rr] += __shfl_xor_sync(0xffffffffu, T0[rr], o);
                    T1[rr] += __shfl_xor_sync(0xffffffffu, T1[rr], o);
                    T2[rr] += __shfl_xor_sync(0xffffffffu, T2[rr], o);
                }
            }
            if (lsub == 0) {
#pragma unroll
                for (int rr = 0; rr < 4; rr++) {
                    int idx = (b << 12) + row0 + rr;
                    g_pS[je][idx]  = S[rr];
                    g_pT0[je][idx] = T0[rr];
                    g_pT1[je][idx] = T1[rr];
                    g_pT2[je][idx] = T2[rr];
                }
            }
        }
    }
}

// ---------------------------------------------------------------------------
// Kernel 3: combine eighths, normalize, ELU
__global__ void k_elu()
{
    int t = blockIdx.x * blockDim.x + threadIdx.x;
    if (t >= NB * NE) return;
    float S = 0.f, v0 = 0.f, v1 = 0.f, v2 = 0.f;
#pragma unroll
    for (int e = 0; e < 8; e++) {
        S  += g_pS[e][t];
        v0 += g_pT0[e][t];
        v1 += g_pT1[e][t];
        v2 += g_pT2[e][t];
    }
    float inv = 1.f / S;
    v0 *= inv; v1 *= inv; v2 *= inv;
    v0 = v0 > 0.f ? v0 : expm1f(v0);
    v1 = v1 > 0.f ? v1 : expm1f(v1);
    v2 = v2 > 0.f ? v2 : expm1f(v2);
    g_x[t * 3 + 0] = v0;
    g_x[t * 3 + 1] = v1;
    g_x[t * 3 + 2] = v2;
}

// ---------------------------------------------------------------------------
// Kernel 4a: FC partial. grid (25, 6). launch_bounds(256,1) -> full reg budget,
// 16 front-batched independent LDG.128 per thread.
__global__ void __launch_bounds__(256, 1) k_fc1(const float* __restrict__ w)
{
    __shared__ float sr[8][16];
    int kg = blockIdx.x, c = blockIdx.y;
    int tid = threadIdx.x;
    int n0 = c * 2048 + tid * 4;

    float4 wv[KG][2];
#pragma unroll
    for (int kk = 0; kk < KG; kk++) {
        const float* wr = w + (size_t)(kg * KG + kk) * (NE * 3);
        wv[kk][0] = __ldg((const float4*)(wr + n0));
        wv[kk][1] = __ldg((const float4*)(wr + n0 + 1024));
    }
    float4 xv[NB][2];
#pragma unroll
    for (int b = 0; b < NB; b++) {
        xv[b][0] = *(const float4*)(g_x + b * NE * 3 + n0);
        xv[b][1] = *(const float4*)(g_x + b * NE * 3 + n0 + 1024);
    }

    float acc[KG][NB];
#pragma unroll
    for (int kk = 0; kk < KG; kk++)
#pragma unroll
        for (int b = 0; b < NB; b++) {
            float a = fmaf(wv[kk][0].x, xv[b][0].x, fmaf(wv[kk][0].y, xv[b][0].y,
                      fmaf(wv[kk][0].z, xv[b][0].z, wv[kk][0].w * xv[b][0].w)));
            a = fmaf(wv[kk][1].x, xv[b][1].x, fmaf(wv[kk][1].y, xv[b][1].y,
                fmaf(wv[kk][1].z, xv[b][1].z, fmaf(wv[kk][1].w, xv[b][1].w, a))));
            acc[kk][b] = a;
        }
#pragma unroll
    for (int o = 16; o > 0; o >>= 1)
#pragma unroll
        for (int kk = 0; kk < KG; kk++)
#pragma unroll
            for (int b = 0; b < NB; b++)
                acc[kk][b] += __shfl_xor_sync(0xffffffffu, acc[kk][b], o);

    int wrp = tid >> 5, lane = tid & 31;
    if (lane == 0) {
#pragma unroll
        for (int kk = 0; kk < KG; kk++)
#pragma unroll
            for (int b = 0; b < NB; b++)
                sr[wrp][kk * NB + b] = acc[kk][b];
    }
    __syncthreads();
    if (tid < KG * NB) {
        float s = 0.f;
#pragma unroll
        for (int ww = 0; ww < 8; ww++) s += sr[ww][tid];
        int kk = tid >> 2, b = tid & 3;
        g_part[c * (FCO * NB) + (kg * KG + kk) * NB + b] = s;
    }
}

__global__ void k_fc2(const float* __restrict__ bias, float* __restrict__ out)
{
    int tid = threadIdx.x;
    if (tid >= FCO * NB) return;
    int k = tid >> 2, b = tid & 3;
    float s = __ldg(bias + k);
#pragma unroll
    for (int c = 0; c < NCH; c++) s += g_part[c * (FCO * NB) + k * NB + b];
    out[b * FCO + k] = s;
}

// ---------------------------------------------------------------------------
extern "C" void kernel_launch(void* const* d_in, const int* in_sizes, int n_in,
                              void* d_out, int out_size)
{
    const int*   adj = (const int*)d_in[0];
    const float* emb = (const float*)d_in[1];
    const float* W   = (const float*)d_in[2];
    const float* av  = (const float*)d_in[3];
    const float* fcw = (const float*)d_in[4];
    const float* fcb = (const float*)d_in[5];
    float* out = (float*)d_out;

    cudaFuncSetAttribute(k_main, cudaFuncAttributeMaxDynamicSharedMemorySize,
                         SMEM_BYTES);

    k_prep<<<NE * 4 / 256, 256>>>(emb, W, av);
    k_main<<<GRID, NTHR, SMEM_BYTES>>>(adj);
    k_elu<<<NB * NE / 256, 256>>>();
    k_fc1<<<dim3(FCO / KG, NCH), 256>>>(fcw);
    k_fc2<<<1, 512>>>(fcb, out);
}

// round 11
// speedup vs baseline: 1.1657x; 1.0221x over previous
#include <cuda_runtime.h>
#include <math.h>

#define NE   4096
#define EMB  64
#define NB   4
#define FCO  100
#define GRID 148
#define NTHR 512
#define NWARP 16
#define NWSLOT (GRID * NWARP)     // 2368 warp slots
#define NITEM 16384               // NB * 512 row-groups(8) * 8 j-eighths
#define TBL_FLOATS (5 * NE)       // q,q2,h0,h1,h2 = 80KB
#define RING_INTS (NWARP * 4 * 512)   // 16 warps x 4 slots x 2KB = 128KB
#define SMEM_BYTES (TBL_FLOATS * 4 + RING_INTS * 4)  // 208KB

// Scratch (allocation-free rule: __device__ globals)
__device__ float g_h0[NE], g_h1[NE], g_h2[NE];
__device__ float g_src[NE], g_dst[NE];
__device__ float g_x[NB * NE * 3];
__device__ float g_pS[8][NB * NE];
__device__ float g_pT0[8][NB * NE], g_pT1[8][NB * NE], g_pT2[8][NB * NE];
__device__ unsigned g_mbits = 0u;   // static init; atomicMax idempotent across replays

__device__ __forceinline__ unsigned enc_f(float f) {
    unsigned b = __float_as_uint(f);
    return (b & 0x80000000u) ? ~b : (b | 0x80000000u);
}
__device__ __forceinline__ float dec_f(unsigned u) {
    unsigned b = (u & 0x80000000u) ? (u & 0x7fffffffu) : ~u;
    return __uint_as_float(b);
}
__device__ __forceinline__ unsigned smem_u32(const void* p) {
    return (unsigned)__cvta_generic_to_shared(p);
}
__device__ __forceinline__ void cp16(unsigned dst, const void* src) {
    asm volatile("cp.async.cg.shared.global [%0], [%1], 16;" :: "r"(dst), "l"(src) : "memory");
}
__device__ __forceinline__ void cp_commit() {
    asm volatile("cp.async.commit_group;" ::: "memory");
}
__device__ __forceinline__ void cp_wait3() {
    asm volatile("cp.async.wait_group 3;" ::: "memory");
}
__device__ __forceinline__ void cp_wait0() {
    asm volatile("cp.async.wait_group 0;" ::: "memory");
}

// Packed f32x2 helpers (sm_103a)
typedef unsigned long long ull;
__device__ __forceinline__ ull pack2(float lo, float hi) {
    ull r; asm("mov.b64 %0, {%1, %2};" : "=l"(r) : "f"(lo), "f"(hi)); return r;
}
__device__ __forceinline__ void unpack2(float& lo, float& hi, ull v) {
    asm("mov.b64 {%0, %1}, %2;" : "=f"(lo), "=f"(hi) : "l"(v));
}
__device__ __forceinline__ ull mul2(ull a, ull b) {
    ull d; asm("mul.rn.f32x2 %0, %1, %2;" : "=l"(d) : "l"(a), "l"(b)); return d;
}
#define FMA_X2(d, a, b, c) \
    asm("fma.rn.f32x2 %0, %1, %2, %3;" : "=l"(d) : "l"(a), "l"(b), "l"(c))
#define ADD_X2(d, a, b) \
    asm("add.rn.f32x2 %0, %1, %2;" : "=l"(d) : "l"(a), "l"(b))

// ---------------------------------------------------------------------------
// Kernel 1: h = emb @ W (4 threads/row), src/dst, global max(dst)
__global__ void __launch_bounds__(256) k_prep(const float* __restrict__ emb,
                                              const float* __restrict__ W,
                                              const float* __restrict__ av)
{
    int t = blockIdx.x * 256 + threadIdx.x;
    int row = t >> 2, sub = t & 3;
    const float4* e4 = (const float4*)(emb + row * EMB);
    float h0 = 0.f, h1 = 0.f, h2 = 0.f;
#pragma unroll
    for (int i = 0; i < 4; i++) {
        int fi = sub + i * 4;
        float4 ev = __ldg(e4 + fi);
        int k = fi * 4;
        h0 = fmaf(ev.x, __ldg(W + (k+0)*3+0), h0); h1 = fmaf(ev.x, __ldg(W + (k+0)*3+1), h1); h2 = fmaf(ev.x, __ldg(W + (k+0)*3+2), h2);
        h0 = fmaf(ev.y, __ldg(W + (k+1)*3+0), h0); h1 = fmaf(ev.y, __ldg(W + (k+1)*3+1), h1); h2 = fmaf(ev.y, __ldg(W + (k+1)*3+2), h2);
        h0 = fmaf(ev.z, __ldg(W + (k+2)*3+0), h0); h1 = fmaf(ev.z, __ldg(W + (k+2)*3+1), h1); h2 = fmaf(ev.z, __ldg(W + (k+2)*3+2), h2);
        h0 = fmaf(ev.w, __ldg(W + (k+3)*3+0), h0); h1 = fmaf(ev.w, __ldg(W + (k+3)*3+1), h1); h2 = fmaf(ev.w, __ldg(W + (k+3)*3+2), h2);
    }
#pragma unroll
    for (int o = 1; o <= 2; o <<= 1) {
        h0 += __shfl_xor_sync(0xffffffffu, h0, o);
        h1 += __shfl_xor_sync(0xffffffffu, h1, o);
        h2 += __shfl_xor_sync(0xffffffffu, h2, o);
    }
    if (sub == 0) {
        g_h0[row] = h0; g_h1[row] = h1; g_h2[row] = h2;
        g_src[row] = h0 * __ldg(av + 0) + h1 * __ldg(av + 1) + h2 * __ldg(av + 2);
        float d    = h0 * __ldg(av + 3) + h1 * __ldg(av + 4) + h2 * __ldg(av + 5);
        g_dst[row] = d;
        atomicMax(&g_mbits, enc_f(d));
    }
}

// ---------------------------------------------------------------------------
// Kernel 2: persistent; per-warp cp.async ring (4 x 2KB), f32x2 math, 8-row items.
// (unchanged from R10 — best measured configuration)
// ---------------------------------------------------------------------------
__global__ void __launch_bounds__(NTHR, 1) k_main(const int* __restrict__ adj)
{
    extern __shared__ float sm[];
    float* sq  = sm;
    float* sq2 = sm + NE;
    float* sh0 = sm + 2 * NE;
    float* sh1 = sm + 3 * NE;
    float* sh2 = sm + 4 * NE;
    int*   ring = (int*)(sm + TBL_FLOATS);

    int tid = threadIdx.x, bid = blockIdx.x;
    int warp = tid >> 5, lane = tid & 31;
    int lsub = lane & 15, halfr0 = (lane >> 4) << 2;
    int wid = bid * NWARP + warp;

    float Md = dec_f(g_mbits);
    for (int i = tid; i < NE; i += NTHR) {
        float d = g_dst[i];
        sq[i]  = expf(d - Md);
        sq2[i] = expf(0.2f * (d - Md));
        sh0[i] = g_h0[i]; sh1[i] = g_h1[i]; sh2[i] = g_h2[i];
    }
    __syncthreads();   // only barrier

    int nItems = 0;
    for (int it = wid; it < NITEM; it += NWSLOT) nItems++;
    int total = nItems * 8;
    if (total == 0) return;

    int* wring = ring + warp * 2048;              // 4 slots x 512 ints
    int cp_row = lane >> 2, cp_col = (lane & 3) << 2;   // ints
    unsigned cp_dst0 = smem_u32(wring) + (unsigned)((cp_row << 6) + cp_col) * 4u;

    auto issue = [&](int step) {
        int it = wid + (step >> 3) * NWSLOT;
        int slot = step & 3;
        int b = it >> 12, grp = (it >> 3) & 511, je = it & 7;
        const int* src = adj
            + ((size_t)((b << 12) + (grp << 3) + cp_row)) * NE
            + (je << 9) + ((step & 7) << 6) + cp_col;
        unsigned dst = cp_dst0 + (unsigned)slot * 2048u;
#pragma unroll
        for (int k = 0; k < 4; k++)
            cp16(dst + k * 64u, src + k * 16);
        cp_commit();
    };

    for (int p = 0; p < 3 && p < total; p++) issue(p);

    ull Sp[4] = {0,0,0,0}, T0p[4] = {0,0,0,0}, T1p[4] = {0,0,0,0}, T2p[4] = {0,0,0,0};
    ull Ca2[4], Cb2[4];
    float W0s[4];

    for (int step = 0; step < total; step++) {
        int it = wid + (step >> 3) * NWSLOT;
        int chunk = step & 7, slot = step & 3;
        int b = it >> 12, grp = (it >> 3) & 511, je = it & 7;
        int row0 = (grp << 3) + halfr0;

        if (chunk == 0) {
#pragma unroll
            for (int rr = 0; rr < 4; rr++) {
                float z  = __ldg(&g_src[row0 + rr]) + Md;
                float lr = z > 0.f ? z : 0.2f * z;
                float Cc = fmaxf(lr, 9e-15f);
                float ca = expf(z - Cc), cb = expf(0.2f * z - Cc);
                Ca2[rr] = pack2(ca, ca);
                Cb2[rr] = pack2(cb, cb);
                W0s[rr] = expf(9e-15f - Cc);
            }
        }

        // independent table loads + m-precompute BEFORE the wait
        int jg = (je << 9) + (chunk << 6) + (lsub << 2);
        double2 Qd  = *(const double2*)(sq  + jg);
        double2 Q2d = *(const double2*)(sq2 + jg);
        double2 H0d = *(const double2*)(sh0 + jg);
        double2 H1d = *(const double2*)(sh1 + jg);
        double2 H2d = *(const double2*)(sh2 + jg);
        ull qlo  = __double_as_longlong(Qd.x),  qhi  = __double_as_longlong(Qd.y);
        ull q2lo = __double_as_longlong(Q2d.x), q2hi = __double_as_longlong(Q2d.y);
        ull h0lo = __double_as_longlong(H0d.x), h0hi = __double_as_longlong(H0d.y);
        ull h1lo = __double_as_longlong(H1d.x), h1hi = __double_as_longlong(H1d.y);
        ull h2lo = __double_as_longlong(H2d.x), h2hi = __double_as_longlong(H2d.y);

        if (step + 3 < total) { issue(step + 3); cp_wait3(); }
        else                  { cp_wait0(); }
        __syncwarp();

        const int* st = wring + slot * 512;
#pragma unroll
        for (int rr = 0; rr < 4; rr++) {
            int4 aa = *(const int4*)(st + ((halfr0 + rr) << 6) + (lsub << 2));
            {
                ull t1 = mul2(Ca2[rr], qlo), t2 = mul2(Cb2[rr], q2lo);
                float m0, m1, n0, n1;
                unpack2(m0, m1, t1); unpack2(n0, n1, t2);
                float w0 = (aa.x > 0) ? fmaxf(m0, n0) : W0s[rr];
                float w1 = (aa.y > 0) ? fmaxf(m1, n1) : W0s[rr];
                ull wp = pack2(w0, w1);
                ADD_X2(Sp[rr], Sp[rr], wp);
                FMA_X2(T0p[rr], wp, h0lo, T0p[rr]);
                FMA_X2(T1p[rr], wp, h1lo, T1p[rr]);
                FMA_X2(T2p[rr], wp, h2lo, T2p[rr]);
            }
            {
                ull t1 = mul2(Ca2[rr], qhi), t2 = mul2(Cb2[rr], q2hi);
                float m0, m1, n0, n1;
                unpack2(m0, m1, t1); unpack2(n0, n1, t2);
                float w0 = (aa.z > 0) ? fmaxf(m0, n0) : W0s[rr];
                float w1 = (aa.w > 0) ? fmaxf(m1, n1) : W0s[rr];
                ull wp = pack2(w0, w1);
                ADD_X2(Sp[rr], Sp[rr], wp);
                FMA_X2(T0p[rr], wp, h0hi, T0p[rr]);
                FMA_X2(T1p[rr], wp, h1hi, T1p[rr]);
                FMA_X2(T2p[rr], wp, h2hi, T2p[rr]);
            }
        }

        if (chunk == 7) {
            float S[4], T0[4], T1[4], T2[4];
#pragma unroll
            for (int rr = 0; rr < 4; rr++) {
                float lo, hi;
                unpack2(lo, hi, Sp[rr]);  S[rr]  = lo + hi;
                unpack2(lo, hi, T0p[rr]); T0[rr] = lo + hi;
                unpack2(lo, hi, T1p[rr]); T1[rr] = lo + hi;
                unpack2(lo, hi, T2p[rr]); T2[rr] = lo + hi;
                Sp[rr] = 0ull; T0p[rr] = 0ull; T1p[rr] = 0ull; T2p[rr] = 0ull;
            }
#pragma unroll
            for (int o = 8; o > 0; o >>= 1) {
#pragma unroll
                for (int rr = 0; rr < 4; rr++) {
                    S[rr]  += __shfl_xor_sync(0xffffffffu, S[rr],  o);
                    T0[rr] += __shfl_xor_sync(0xffffffffu, T0[rr], o);
                    T1[rr] += __shfl_xor_sync(0xffffffffu, T1[rr], o);
                    T2[rr] += __shfl_xor_sync(0xffffffffu, T2[rr], o);
                }
            }
            if (lsub == 0) {
#pragma unroll
                for (int rr = 0; rr < 4; rr++) {
                    int idx = (b << 12) + row0 + rr;
                    g_pS[je][idx]  = S[rr];
                    g_pT0[je][idx] = T0[rr];
                    g_pT1[je][idx] = T1[rr];
                    g_pT2[je][idx] = T2[rr];
                }
            }
        }
    }
}

// ---------------------------------------------------------------------------
// Kernel 3: combine eighths, normalize, ELU
__global__ void k_elu()
{
    int t = blockIdx.x * blockDim.x + threadIdx.x;
    if (t >= NB * NE) return;
    float S = 0.f, v0 = 0.f, v1 = 0.f, v2 = 0.f;
#pragma unroll
    for (int e = 0; e < 8; e++) {
        S  += g_pS[e][t];
        v0 += g_pT0[e][t];
        v1 += g_pT1[e][t];
        v2 += g_pT2[e][t];
    }
    float inv = 1.f / S;
    v0 *= inv; v1 *= inv; v2 *= inv;
    v0 = v0 > 0.f ? v0 : expm1f(v0);
    v1 = v1 > 0.f ? v1 : expm1f(v1);
    v2 = v2 > 0.f ? v2 : expm1f(v2);
    g_x[t * 3 + 0] = v0;
    g_x[t * 3 + 1] = v1;
    g_x[t * 3 + 2] = v2;
}

// ---------------------------------------------------------------------------
// Kernel 4: single-wave full FC. grid=100 (one block per k), block=256.
// All 12 w-float4 front-batched (one DRAM round), then 3 chunks of L2-hot x.
__global__ void __launch_bounds__(256, 1) k_fc(const float* __restrict__ w,
                                               const float* __restrict__ bias,
                                               float* __restrict__ out)
{
    __shared__ float sr[8][4];
    int k = blockIdx.x, tid = threadIdx.x;
    const float* wr = w + (size_t)k * (NE * 3);

    float4 wv[12];
#pragma unroll
    for (int i = 0; i < 12; i++)
        wv[i] = __ldg((const float4*)(wr + i * 1024 + tid * 4));

    float acc[NB] = {0.f, 0.f, 0.f, 0.f};
#pragma unroll
    for (int c = 0; c < 3; c++) {
        float4 xv[NB][4];
#pragma unroll
        for (int b = 0; b < NB; b++)
#pragma unroll
            for (int i = 0; i < 4; i++)
                xv[b][i] = *(const float4*)(g_x + b * NE * 3 + (c * 4 + i) * 1024 + tid * 4);
#pragma unroll
        for (int b = 0; b < NB; b++)
#pragma unroll
            for (int i = 0; i < 4; i++) {
                float4 wvv = wv[c * 4 + i];
                acc[b] = fmaf(wvv.x, xv[b][i].x, fmaf(wvv.y, xv[b][i].y,
                         fmaf(wvv.z, xv[b][i].z, fmaf(wvv.w, xv[b][i].w, acc[b]))));
            }
    }
#pragma unroll
    for (int o = 16; o > 0; o >>= 1)
#pragma unroll
        for (int b = 0; b < NB; b++)
            acc[b] += __shfl_xor_sync(0xffffffffu, acc[b], o);

    int wrp = tid >> 5, lane = tid & 31;
    if (lane == 0) {
#pragma unroll
        for (int b = 0; b < NB; b++) sr[wrp][b] = acc[b];
    }
    __syncthreads();
    if (tid < NB) {
        float s = __ldg(bias + k);
#pragma unroll
        for (int ww = 0; ww < 8; ww++) s += sr[ww][tid];
        out[tid * FCO + k] = s;
    }
}

// ---------------------------------------------------------------------------
extern "C" void kernel_launch(void* const* d_in, const int* in_sizes, int n_in,
                              void* d_out, int out_size)
{
    const int*   adj = (const int*)d_in[0];
    const float* emb = (const float*)d_in[1];
    const float* W   = (const float*)d_in[2];
    const float* av  = (const float*)d_in[3];
    const float* fcw = (const float*)d_in[4];
    const float* fcb = (const float*)d_in[5];
    float* out = (float*)d_out;

    cudaFuncSetAttribute(k_main, cudaFuncAttributeMaxDynamicSharedMemorySize,
                         SMEM_BYTES);

    k_prep<<<NE * 4 / 256, 256>>>(emb, W, av);
    k_main<<<GRID, NTHR, SMEM_BYTES>>>(adj);
    k_elu<<<NB * NE / 256, 256>>>();
    k_fc<<<FCO, 256>>>(fcw, fcb, out);
}